// round 2
// baseline (speedup 1.0000x reference)
#include <cuda_runtime.h>
#include <math.h>

#define NROWS 8192
#define NCOLS 8192
#define BC 128                 // columns per block tile
#define BR 64                  // rows per block tile
#define GX (NCOLS / BC)        // 64
#define GY (NROWS / BR)        // 128
#define NBLK (GX * GY)         // 8192

// Scratch (no allocation allowed in kernel_launch; __device__ globals are the rule)
__device__ float g_rowsum[NROWS];
__device__ float g_colsum[NCOLS];
__device__ float g_s1part[NBLK];

__global__ void mi_zero_kernel() {
    int i = blockIdx.x * blockDim.x + threadIdx.x;
    if (i < NROWS) g_rowsum[i] = 0.0f;
    if (i < NCOLS) g_colsum[i] = 0.0f;
}

__global__ __launch_bounds__(256) void mi_main_kernel(const float* __restrict__ ct) {
    const int tx  = threadIdx.x;          // 0..31  (one warp per ty)
    const int ty  = threadIdx.y;          // 0..7
    const int lin = ty * 32 + tx;
    const int c0  = blockIdx.x * BC;
    const int r0  = blockIdx.y * BR;
    const int col = c0 + tx * 4;

    float ca0 = 0.f, ca1 = 0.f, ca2 = 0.f, ca3 = 0.f;   // column partials (4 owned cols)
    float s1  = 0.f;                                     // sum c*log2(c)

    #pragma unroll
    for (int it = 0; it < BR / 8; ++it) {
        const int r = r0 + it * 8 + ty;
        float4 v = __ldcs(reinterpret_cast<const float4*>(ct + (size_t)r * NCOLS + col));

        s1 += (v.x > 0.f) ? v.x * __log2f(v.x) : 0.f;
        s1 += (v.y > 0.f) ? v.y * __log2f(v.y) : 0.f;
        s1 += (v.z > 0.f) ? v.z * __log2f(v.z) : 0.f;
        s1 += (v.w > 0.f) ? v.w * __log2f(v.w) : 0.f;

        ca0 += v.x; ca1 += v.y; ca2 += v.z; ca3 += v.w;

        // row partial for this row across the warp's 128 columns
        float rs = (v.x + v.y) + (v.z + v.w);
        #pragma unroll
        for (int o = 16; o > 0; o >>= 1)
            rs += __shfl_xor_sync(0xffffffffu, rs, o);
        if (tx == 0) atomicAdd(&g_rowsum[r], rs);
    }

    // ---- column partials: reduce across the 8 ty-slices via shared, then 1 atomic/col
    __shared__ float4 scol4[8][32];
    scol4[ty][tx] = make_float4(ca0, ca1, ca2, ca3);
    __syncthreads();
    if (lin < BC) {
        const float* sc = reinterpret_cast<const float*>(scol4);
        float t = 0.f;
        #pragma unroll
        for (int k = 0; k < 8; ++k) t += sc[k * BC + lin];
        atomicAdd(&g_colsum[c0 + lin], t);
    }

    // ---- S1 block reduce -> plain store (no global contention)
    #pragma unroll
    for (int o = 16; o > 0; o >>= 1)
        s1 += __shfl_xor_sync(0xffffffffu, s1, o);
    __shared__ float sw[8];
    if (tx == 0) sw[ty] = s1;
    __syncthreads();
    if (lin == 0) {
        float t = 0.f;
        #pragma unroll
        for (int k = 0; k < 8; ++k) t += sw[k];
        g_s1part[blockIdx.y * gridDim.x + blockIdx.x] = t;
    }
}

__global__ __launch_bounds__(1024) void mi_final_kernel(float* __restrict__ out) {
    const int t = threadIdx.x;
    double acc = 0.0;

    for (int i = t; i < NROWS; i += 1024) {
        float v = g_rowsum[i];
        if (v > 0.f) acc -= (double)v * log2((double)v);
    }
    for (int i = t; i < NCOLS; i += 1024) {
        float v = g_colsum[i];
        if (v > 0.f) acc -= (double)v * log2((double)v);
    }
    for (int i = t; i < NBLK; i += 1024) acc += (double)g_s1part[i];

    // block reduce in double
    #pragma unroll
    for (int o = 16; o > 0; o >>= 1)
        acc += __shfl_xor_sync(0xffffffffu, acc, o);
    __shared__ double sd[32];
    if ((t & 31) == 0) sd[t >> 5] = acc;
    __syncthreads();
    if (t < 32) {
        double a = sd[t];
        #pragma unroll
        for (int o = 16; o > 0; o >>= 1)
            a += __shfl_xor_sync(0xffffffffu, a, o);
        if (t == 0) out[0] = (float)a;
    }
}

extern "C" void kernel_launch(void* const* d_in, const int* in_sizes, int n_in,
                              void* d_out, int out_size) {
    const float* ct = (const float*)d_in[0];
    float* out = (float*)d_out;

    mi_zero_kernel<<<(NROWS + 255) / 256, 256>>>();

    dim3 grid(GX, GY);
    dim3 block(32, 8);
    mi_main_kernel<<<grid, block>>>(ct);

    mi_final_kernel<<<1, 1024>>>(out);
}

// round 4
// speedup vs baseline: 1.2187x; 1.2187x over previous
#include <cuda_runtime.h>
#include <math.h>

#define NROWS 8192
#define NCOLS 8192
#define BC 128                 // columns per block tile
#define BR 64                  // rows per block tile
#define GX (NCOLS / BC)        // 64
#define GY (NROWS / BR)        // 128
#define NBLK (GX * GY)         // 8192

// Scratch state. Invariant: all-zero at kernel_launch entry; the last block
// restores zeros after consuming, so every call (correctness run and each
// graph replay) sees identical initial state -> deterministic.
__device__ float g_rowsum[NROWS];
__device__ float g_colsum[NCOLS];
__device__ float g_s1part[NBLK];
__device__ unsigned int g_count;

__global__ __launch_bounds__(256) void mi_fused_kernel(const float* __restrict__ ct,
                                                       float* __restrict__ out) {
    const int tx  = threadIdx.x;          // 0..31
    const int ty  = threadIdx.y;          // 0..7
    const int lin = ty * 32 + tx;
    const int c0  = blockIdx.x * BC;
    const int r0  = blockIdx.y * BR;
    const int col = c0 + tx * 4;

    __shared__ float srow[BR][33];        // padded: bank = (row+tx)%32, conflict-free

    float ca0 = 0.f, ca1 = 0.f, ca2 = 0.f, ca3 = 0.f;
    float s1a = 0.f, s1b = 0.f, s1c = 0.f, s1d = 0.f;

    // ---- streaming loop: loads + math only, NO cross-lane ops ----
    #pragma unroll
    for (int it = 0; it < BR / 8; ++it) {
        const int r = r0 + it * 8 + ty;
        float4 v = __ldcs(reinterpret_cast<const float4*>(ct + (size_t)r * NCOLS + col));

        s1a += (v.x > 0.f) ? v.x * __log2f(v.x) : 0.f;
        s1b += (v.y > 0.f) ? v.y * __log2f(v.y) : 0.f;
        s1c += (v.z > 0.f) ? v.z * __log2f(v.z) : 0.f;
        s1d += (v.w > 0.f) ? v.w * __log2f(v.w) : 0.f;

        ca0 += v.x; ca1 += v.y; ca2 += v.z; ca3 += v.w;

        srow[it * 8 + ty][tx] = (v.x + v.y) + (v.z + v.w);
    }
    __syncthreads();

    // ---- row partials: 4 lanes per row, 8 LDS each, 2 shuffles, 1 atomic/row ----
    {
        const int row = lin >> 2;         // 0..63
        const int q   = lin & 3;          // 0..3
        float t = 0.f;
        #pragma unroll
        for (int k = 0; k < 8; ++k) t += srow[row][q * 8 + k];
        t += __shfl_xor_sync(0xffffffffu, t, 1);
        t += __shfl_xor_sync(0xffffffffu, t, 2);
        if (q == 0) atomicAdd(&g_rowsum[r0 + row], t);
    }

    // ---- column partials: smem transpose-reduce, 1 atomic/col ----
    __shared__ float4 scol4[8][32];
    scol4[ty][tx] = make_float4(ca0, ca1, ca2, ca3);
    __syncthreads();
    if (lin < BC) {
        const float* sc = reinterpret_cast<const float*>(scol4);
        float t = 0.f;
        #pragma unroll
        for (int k = 0; k < 8; ++k) t += sc[k * BC + lin];
        atomicAdd(&g_colsum[c0 + lin], t);
    }

    // ---- S1 block partial -> plain store ----
    {
        float s1 = (s1a + s1b) + (s1c + s1d);
        #pragma unroll
        for (int o = 16; o > 0; o >>= 1)
            s1 += __shfl_xor_sync(0xffffffffu, s1, o);
        __shared__ float sw[8];
        if (tx == 0) sw[ty] = s1;
        __syncthreads();
        if (lin == 0) {
            float t = 0.f;
            #pragma unroll
            for (int k = 0; k < 8; ++k) t += sw[k];
            g_s1part[blockIdx.y * gridDim.x + blockIdx.x] = t;
        }
    }

    // ---- last-block completion (threadfence reduction pattern) ----
    __shared__ unsigned int is_last;
    __threadfence();
    __syncthreads();
    if (lin == 0) {
        unsigned int old = atomicAdd(&g_count, 1u);
        is_last = (old == (unsigned int)(NBLK - 1)) ? 1u : 0u;
    }
    __syncthreads();
    if (!is_last) return;

    __threadfence();  // acquire side: see all blocks' writes

    double acc = 0.0;
    for (int i = lin; i < NROWS; i += 256) {
        float v = g_rowsum[i];
        if (v > 0.f) acc -= (double)v * (double)__log2f(v);
        g_rowsum[i] = 0.0f;               // restore invariant
    }
    for (int i = lin; i < NCOLS; i += 256) {
        float v = g_colsum[i];
        if (v > 0.f) acc -= (double)v * (double)__log2f(v);
        g_colsum[i] = 0.0f;               // restore invariant
    }
    for (int i = lin; i < NBLK; i += 256)
        acc += (double)g_s1part[i];       // overwritten each run, no zeroing

    // block reduce 256 doubles
    #pragma unroll
    for (int o = 16; o > 0; o >>= 1)
        acc += __shfl_xor_sync(0xffffffffu, acc, o);
    __shared__ double sd[8];
    if (tx == 0) sd[ty] = acc;
    __syncthreads();
    if (lin == 0) {
        double a = 0.0;
        #pragma unroll
        for (int k = 0; k < 8; ++k) a += sd[k];
        out[0] = (float)a;
        g_count = 0u;                     // restore invariant
    }
}

extern "C" void kernel_launch(void* const* d_in, const int* in_sizes, int n_in,
                              void* d_out, int out_size) {
    const float* ct = (const float*)d_in[0];
    float* out = (float*)d_out;

    dim3 grid(GX, GY);
    dim3 block(32, 8);
    mi_fused_kernel<<<grid, block>>>(ct, out);
}

// round 5
// speedup vs baseline: 1.2587x; 1.0328x over previous
#include <cuda_runtime.h>
#include <math.h>

#define NROWS 8192
#define NCOLS 8192
#define BC 128                 // columns per block tile
#define BR 64                  // rows per block tile
#define GX (NCOLS / BC)        // 64
#define GY (NROWS / BR)        // 128
#define NBLK (GX * GY)         // 8192

// Scratch state. Invariant: all-zero at kernel_launch entry; the last block
// restores zeros after consuming, so every call (correctness run and each
// graph replay) sees identical initial state -> deterministic.
__device__ float g_rowsum[NROWS];
__device__ float g_colsum[NCOLS];
__device__ float g_s1part[NBLK];
__device__ unsigned int g_count;

__global__ __launch_bounds__(256) void mi_fused_kernel(const float* __restrict__ ct,
                                                       float* __restrict__ out) {
    const int tx  = threadIdx.x;          // 0..31
    const int ty  = threadIdx.y;          // 0..7
    const int lin = ty * 32 + tx;
    const int c0  = blockIdx.x * BC;
    const int r0  = blockIdx.y * BR;
    const int col = c0 + tx * 4;

    __shared__ float srow[BR][33];        // padded: conflict-free

    // ---- batch all 8 independent 128-bit loads first (MLP_p1 = 8) ----
    float4 v[8];
    const float* base = ct + (size_t)(r0 + ty) * NCOLS + col;
    #pragma unroll
    for (int it = 0; it < 8; ++it)
        v[it] = __ldcs(reinterpret_cast<const float4*>(base + (size_t)it * 8 * NCOLS));

    float ca0 = 0.f, ca1 = 0.f, ca2 = 0.f, ca3 = 0.f;
    float s1a = 0.f, s1b = 0.f, s1c = 0.f, s1d = 0.f;

    // ---- lean math pass: MUFU + FFMA + FMNMX + FADD per element ----
    #pragma unroll
    for (int it = 0; it < 8; ++it) {
        float x = v[it].x, y = v[it].y, z = v[it].z, w = v[it].w;
        // inputs are >= 0; nonzero values are >= 2^-24, so fmaxf(v,1e-30) == v
        // for all nonzero v, and v==0 contributes 0 * log2(1e-30) = 0.
        s1a = __fmaf_rn(x, __log2f(fmaxf(x, 1e-30f)), s1a);
        s1b = __fmaf_rn(y, __log2f(fmaxf(y, 1e-30f)), s1b);
        s1c = __fmaf_rn(z, __log2f(fmaxf(z, 1e-30f)), s1c);
        s1d = __fmaf_rn(w, __log2f(fmaxf(w, 1e-30f)), s1d);

        ca0 += x; ca1 += y; ca2 += z; ca3 += w;

        srow[it * 8 + ty][tx] = (x + y) + (z + w);
    }
    __syncthreads();

    // ---- row partials: 4 lanes per row, 8 LDS each, 2 shuffles, 1 atomic/row ----
    {
        const int row = lin >> 2;         // 0..63
        const int q   = lin & 3;          // 0..3
        float t = 0.f;
        #pragma unroll
        for (int k = 0; k < 8; ++k) t += srow[row][q * 8 + k];
        t += __shfl_xor_sync(0xffffffffu, t, 1);
        t += __shfl_xor_sync(0xffffffffu, t, 2);
        if (q == 0) atomicAdd(&g_rowsum[r0 + row], t);
    }

    // ---- column partials: smem transpose-reduce, 1 atomic/col ----
    __shared__ float4 scol4[8][32];
    scol4[ty][tx] = make_float4(ca0, ca1, ca2, ca3);
    __syncthreads();
    if (lin < BC) {
        const float* sc = reinterpret_cast<const float*>(scol4);
        float t = 0.f;
        #pragma unroll
        for (int k = 0; k < 8; ++k) t += sc[k * BC + lin];
        atomicAdd(&g_colsum[c0 + lin], t);
    }

    // ---- S1 block partial -> plain store ----
    {
        float s1 = (s1a + s1b) + (s1c + s1d);
        #pragma unroll
        for (int o = 16; o > 0; o >>= 1)
            s1 += __shfl_xor_sync(0xffffffffu, s1, o);
        __shared__ float sw[8];
        if (tx == 0) sw[ty] = s1;
        __syncthreads();
        if (lin == 0) {
            float t = 0.f;
            #pragma unroll
            for (int k = 0; k < 8; ++k) t += sw[k];
            g_s1part[blockIdx.y * gridDim.x + blockIdx.x] = t;
        }
    }

    // ---- last-block completion (threadfence reduction pattern) ----
    __shared__ unsigned int is_last;
    __threadfence();
    __syncthreads();
    if (lin == 0) {
        unsigned int old = atomicAdd(&g_count, 1u);
        is_last = (old == (unsigned int)(NBLK - 1)) ? 1u : 0u;
    }
    __syncthreads();
    if (!is_last) return;

    __threadfence();  // acquire side: see all blocks' writes

    double acc = 0.0;
    for (int i = lin; i < NROWS; i += 256) {
        float s = g_rowsum[i];
        if (s > 0.f) acc -= (double)s * (double)__log2f(s);
        g_rowsum[i] = 0.0f;               // restore invariant
    }
    for (int i = lin; i < NCOLS; i += 256) {
        float s = g_colsum[i];
        if (s > 0.f) acc -= (double)s * (double)__log2f(s);
        g_colsum[i] = 0.0f;               // restore invariant
    }
    for (int i = lin; i < NBLK; i += 256)
        acc += (double)g_s1part[i];       // overwritten each run, no zeroing

    // block reduce 256 doubles
    #pragma unroll
    for (int o = 16; o > 0; o >>= 1)
        acc += __shfl_xor_sync(0xffffffffu, acc, o);
    __shared__ double sd[8];
    if (tx == 0) sd[ty] = acc;
    __syncthreads();
    if (lin == 0) {
        double a = 0.0;
        #pragma unroll
        for (int k = 0; k < 8; ++k) a += sd[k];
        out[0] = (float)a;
        g_count = 0u;                     // restore invariant
    }
}

extern "C" void kernel_launch(void* const* d_in, const int* in_sizes, int n_in,
                              void* d_out, int out_size) {
    const float* ct = (const float*)d_in[0];
    float* out = (float*)d_out;

    dim3 grid(GX, GY);
    dim3 block(32, 8);
    mi_fused_kernel<<<grid, block>>>(ct, out);
}